// round 9
// baseline (speedup 1.0000x reference)
#include <cuda_runtime.h>
#include <cstdint>
#include <math.h>

#define DEV_INLINE __device__ __forceinline__

static constexpr int B_ = 16, C_ = 256, H_ = 128, W_ = 128;
static constexpr int CS = 512;
static constexpr int TOK_HF = 1024;
static constexpr int M_HF = 3 * B_ * TOK_HF;     // 49152
static constexpr int M_LF = B_ * 256;            // 4096

// ---------------- scratch ----------------
__device__ float g_z[3ULL * B_ * C_ * TOK_HF];       // [band][b][c][tok]
__device__ float g_ps[(size_t)B_ * CS * 256];        // [b][s][tok]
__device__ float g_GT[(size_t)M_HF * 512];           // [m][0:256)=G, [256:512)=T
__device__ float g_GTlf[(size_t)M_LF * 512];
__device__ float g_ktok[(size_t)M_LF * C_];
__device__ float g_gate[(size_t)M_LF * C_];
__device__ float g_alpha[3 * B_ * TOK_HF];
__device__ float g_wt[5ULL * 512 * 256];             // transposed weights [n][k]
__device__ float g_BT[2ULL * 512 * 256];             // [chain][n][k]: rows 0-255 W12t, 256-511 Qt
__device__ float g_c1[2 * 256];
__device__ float g_bp[2 * 256];
__device__ float g_bw2[2 * 256];                     // b1 @ W2'
__device__ float g_w1rs[2 * 256];                    // row sums of W1
__device__ float g_w1b1[2 * 256];                    // W1 @ b1
__device__ float g_sc[4];                            // {b1sum, b1sqsum} x chain
__device__ float g_zero[512];                        // stays zero

// ---------------- weight transpose (+ LN-weight folding) ----------------
__global__ void transpose5_kernel(const float* __restrict__ w0, const float* __restrict__ w1,
                                  const float* __restrict__ w2, const float* __restrict__ w3,
                                  const float* __restrict__ w4,
                                  const float* __restrict__ hf_lnw, const float* __restrict__ lf_lnw)
{
    __shared__ float tile[32][33];
    int mi = blockIdx.z;
    const float* in; int R, Cc; const float* lnw = nullptr;
    switch (mi) {
        case 0: in = w0; R = 256; Cc = 512; break;
        case 1: in = w1; R = 512; Cc = 256; lnw = hf_lnw; break;
        case 2: in = w2; R = 512; Cc = 256; break;
        case 3: in = w3; R = 256; Cc = 512; break;
        default: in = w4; R = 512; Cc = 256; lnw = lf_lnw; break;
    }
    float* out = g_wt + (size_t)mi * 512 * 256;
    int bx = blockIdx.x * 32, by = blockIdx.y * 32;
    if (bx >= Cc || by >= R) return;
    int tx = threadIdx.x, ty = threadIdx.y;
#pragma unroll
    for (int j = 0; j < 32; j += 8) {
        int row = by + ty + j;
        float v = in[(size_t)row * Cc + bx + tx];
        if (lnw) v *= __ldg(lnw + row);
        tile[ty + j][tx] = v;
    }
    __syncthreads();
#pragma unroll
    for (int j = 0; j < 32; j += 8)
        out[(size_t)(bx + ty + j) * R + by + tx] = tile[tx][ty + j];
}

// fold: c1[n]=sum_k W2'[k][n]; bp[n]=b2[n]+sum_k lnb_k W2[k][n]; bw2[n]=sum_k b1_k W2'[k][n]
__global__ void fold_kernel(const float* __restrict__ w2a, const float* __restrict__ lnba,
                            const float* __restrict__ b2a, const float* __restrict__ b1a,
                            const float* __restrict__ w2b, const float* __restrict__ lnbb,
                            const float* __restrict__ b2b, const float* __restrict__ b1b)
{
    int mi = blockIdx.x;
    int n = threadIdx.x;
    const float* wt = g_wt + (size_t)(mi ? 4 : 1) * 512 * 256;
    const float* w2 = mi ? w2b : w2a;
    const float* lnb = mi ? lnbb : lnba;
    const float* b2 = mi ? b2b : b2a;
    const float* b1 = mi ? b1b : b1a;
    float s1 = 0.f, s2 = 0.f, s3 = 0.f;
    for (int k = 0; k < 512; k++) {
        float w = wt[(size_t)n * 512 + k];
        s1 += w;
        s2 += lnb[k] * w2[(size_t)k * 256 + n];
        s3 += b1[k] * w;
    }
    g_c1[mi * 256 + n] = s1;
    g_bp[mi * 256 + n] = b2[n] + s2;
    g_bw2[mi * 256 + n] = s3;
}

// fold2: w1rs[k]=sum_j W1[k][j]; w1b1[k]=sum_j W1[k][j] b1[j]; scalars sum(b1), sum(b1^2)
__global__ void fold2_kernel(const float* __restrict__ w1a, const float* __restrict__ b1a,
                             const float* __restrict__ w1b, const float* __restrict__ b1b)
{
    __shared__ float r1[256], r2[256];
    int mi = blockIdx.x;
    int k = threadIdx.x;
    const float* w1 = mi ? w1b : w1a;
    const float* b1 = mi ? b1b : b1a;
    float s1 = 0.f, s2 = 0.f;
    for (int j = 0; j < 512; j++) {
        float w = w1[(size_t)k * 512 + j];
        s1 += w; s2 += w * b1[j];
    }
    g_w1rs[mi * 256 + k] = s1;
    g_w1b1[mi * 256 + k] = s2;
    float a0 = b1[k], a1 = b1[k + 256];
    r1[k] = a0 + a1; r2[k] = a0 * a0 + a1 * a1;
    __syncthreads();
    for (int o = 128; o; o >>= 1) {
        if (k < o) { r1[k] += r1[k + o]; r2[k] += r2[k + o]; }
        __syncthreads();
    }
    if (k == 0) { g_sc[mi * 2 + 0] = r1[0]; g_sc[mi * 2 + 1] = r2[0]; }
}

// prep: BT[chain][n][k] = dot(arow_n, W1_row_k) over c in 512 (fp32 exact-ish)
__global__ void __launch_bounds__(128) prep_dot_kernel(const float* __restrict__ hf_w1,
                                                       const float* __restrict__ lf_w1)
{
    __shared__ __align__(16) float As[512];
    int n = blockIdx.x;        // 0..511
    int chain = blockIdx.y;    // 0 hf, 1 lf
    const float* w1 = chain ? lf_w1 : hf_w1;
    const float* wtm = g_wt + (size_t)(chain ? 4 : 1) * 512 * 256;
    const float* arow = (n < 256) ? (wtm + (size_t)n * 512) : (w1 + (size_t)(n - 256) * 512);
    int t = threadIdx.x;
    ((float4*)As)[t] = ((const float4*)arow)[t];
    __syncthreads();
    float* outb = g_BT + (size_t)chain * 512 * 256 + (size_t)n * 256;
#pragma unroll
    for (int kk = 0; kk < 2; kk++) {
        int k = t + kk * 128;
        const float4* br = (const float4*)(w1 + (size_t)k * 512);
        float s = 0.f;
#pragma unroll 8
        for (int j = 0; j < 128; j++) {
            float4 a = ((const float4*)As)[j];
            float4 b = br[j];
            s += a.x * b.x + a.y * b.y + a.z * b.z + a.w * b.w;
        }
        outb[k] = s;
    }
}

// ---------------- K1: Haar bands -> abs-pooled z tokens ----------------
__global__ void haar_z_kernel(const float* __restrict__ xb)
{
    int tid = threadIdx.x;
    int tk = blockIdx.x * 256 + tid;
    int c = blockIdx.y, b = blockIdx.z;
    int ti = tk >> 5, tj = tk & 31;
    const float* base = xb + ((size_t)(b * C_ + c) * H_ + 4 * ti) * W_ + 4 * tj;
    float4 r0 = *(const float4*)(base);
    float4 r1 = *(const float4*)(base + W_);
    float4 r2 = *(const float4*)(base + 2 * W_);
    float4 r3 = *(const float4*)(base + 3 * W_);
    float zh = 0.f, zv = 0.f, zd = 0.f;
#define HBLK(p00, p01, p10, p11) \
    zh += fabsf((p00) - (p01) + (p10) - (p11)); \
    zv += fabsf((p00) + (p01) - (p10) - (p11)); \
    zd += fabsf((p00) - (p01) - (p10) + (p11));
    HBLK(r0.x, r0.y, r1.x, r1.y)
    HBLK(r0.z, r0.w, r1.z, r1.w)
    HBLK(r2.x, r2.y, r3.x, r3.y)
    HBLK(r2.z, r2.w, r3.z, r3.w)
#undef HBLK
    const float s = 0.0625f;
    size_t base_o = ((size_t)(b) * C_ + c) * TOK_HF + tk;
    const size_t BS = (size_t)B_ * C_ * TOK_HF;
    g_z[base_o]          = zh * s;
    g_z[BS + base_o]     = zv * s;
    g_z[2 * BS + base_o] = zd * s;
}

// ---------------- K2: 4x4 mean-pool of x_small ----------------
__global__ void pool_small_kernel(const float* __restrict__ xsm)
{
    int s = blockIdx.x, b = blockIdx.y;
    const float* src = xsm + ((size_t)(b * CS + s)) * 64 * 64;
    int t = threadIdx.x;
    int tj = t & 15, ti = t >> 4;
    float sum = 0.f;
#pragma unroll
    for (int r = 0; r < 4; r++) {
        float4 v = *(const float4*)(src + (4 * ti + r) * 64 + 4 * tj);
        sum += v.x + v.y + v.z + v.w;
    }
    g_ps[((size_t)(b * CS + s)) * 256 + t] = sum * (1.f / 16.f);
}

// ---------------- mma.sync helpers ----------------
DEV_INLINE void mma8(float* c, const unsigned* a, const unsigned* b) {
    asm volatile("mma.sync.aligned.m16n8k8.row.col.f32.tf32.tf32.f32 "
                 "{%0,%1,%2,%3}, {%4,%5,%6,%7}, {%8,%9}, {%0,%1,%2,%3};"
                 : "+f"(c[0]), "+f"(c[1]), "+f"(c[2]), "+f"(c[3])
                 : "r"(a[0]), "r"(a[1]), "r"(a[2]), "r"(a[3]),
                   "r"(b[0]), "r"(b[1]));
}
DEV_INLINE void ldsm4(unsigned& r0, unsigned& r1, unsigned& r2, unsigned& r3, uint32_t addr) {
    asm volatile("ldmatrix.sync.aligned.m8n8.x4.shared.b16 {%0,%1,%2,%3}, [%4];"
                 : "=r"(r0), "=r"(r1), "=r"(r2), "=r"(r3) : "r"(addr));
}
DEV_INLINE void cp16(uint32_t s, const void* g) {
    asm volatile("cp.async.cg.shared.global [%0], [%1], 16;" :: "r"(s), "l"(g));
}
DEV_INLINE void cp_commit() { asm volatile("cp.async.commit_group;"); }
template<int NN> DEV_INLINE void cp_wait() { asm volatile("cp.async.wait_group %0;" :: "n"(NN)); }

// ---------------- mma.sync 64x256-tile GEMM (R6-proven, EPI=0 only) ----------------
template<int K, int AMODE, int OSTRIDE>
__global__ void __launch_bounds__(256, 2)
gemm256_kernel(const float* __restrict__ A, const float* __restrict__ Bt,
               const float* __restrict__ bias, float* __restrict__ out)
{
    constexpr int KC = 32, SW = 36, SWB = SW * 4, NIT = K / KC, NN = 256;
    constexpr int MT = 2;

    extern __shared__ __align__(16) float dsm[];
    float* As = dsm;
    float* Bs = As + 2 * 64 * SW;

    int tid = threadIdx.x;
    int lane = tid & 31, warp = tid >> 5;
    int wn = warp & 3, wm = warp >> 2;
    int gid = lane >> 2, q4 = lane & 3;
    int m0 = blockIdx.x * 64;
    int n0 = blockIdx.y * 256;

    const float* Ab; int astride = 0;
    if (AMODE == 0) { Ab = A + (size_t)(m0 >> 10) * (C_ * TOK_HF) + (m0 & 1023); astride = TOK_HF; }
    else if (AMODE == 1) { Ab = A + (size_t)(m0 >> 8) * (CS * 256) + (m0 & 255); astride = 256; }
    else { Ab = A + (size_t)m0 * K; }
    const float* BtB = Bt + (size_t)n0 * K;

    uint32_t smem_a = (uint32_t)__cvta_generic_to_shared(As);
    uint32_t smem_b = (uint32_t)__cvta_generic_to_shared(Bs);

    int la_m = tid & 63, la_kg = tid >> 6;
    float areg[8];
    auto load_A = [&](int k0) {
        if (AMODE <= 1) {
#pragma unroll
            for (int i = 0; i < 8; i++)
                areg[i] = __ldg(Ab + (size_t)(k0 + la_kg * 8 + i) * astride + la_m);
        }
    };
    auto sts_A = [&](int st) {
        if (AMODE <= 1) {
            float* p = As + st * 64 * SW + la_m * SW + la_kg * 8;
            *(float4*)(p)     = make_float4(areg[0], areg[1], areg[2], areg[3]);
            *(float4*)(p + 4) = make_float4(areg[4], areg[5], areg[6], areg[7]);
        }
    };
    auto cp_stage = [&](int st, int k0) {
        if (AMODE == 2) {
#pragma unroll
            for (int j = 0; j < 2; j++) {
                int idx = tid + j * 256;
                int m = idx >> 3, kq = idx & 7;
                cp16(smem_a + (uint32_t)((st * 64 + m) * SW + kq * 4) * 4,
                     Ab + (size_t)m * K + k0 + kq * 4);
            }
        }
#pragma unroll
        for (int j = 0; j < 8; j++) {
            int idx = tid + j * 256;
            int n = idx >> 3, kc = idx & 7;
            cp16(smem_b + (uint32_t)((st * NN + n) * SW + kc * 4) * 4,
                 BtB + (size_t)n * K + k0 + kc * 4);
        }
        cp_commit();
    };

    int ra = lane & 15;
    int ca = (lane & 16) ? 16 : 0;
    int rb = (lane & 7) + ((lane >> 4) << 3);
    int cb = (lane & 8) ? 16 : 0;

    float acc[MT][8][4];
#pragma unroll
    for (int mi = 0; mi < MT; mi++)
#pragma unroll
        for (int ni = 0; ni < 8; ni++)
#pragma unroll
            for (int e = 0; e < 4; e++) acc[mi][ni][e] = 0.f;

    load_A(0);
    cp_stage(0, 0);
    sts_A(0);
    if (NIT > 1) load_A(KC);

    for (int it = 0; it < NIT; it++) {
        int cur = it & 1;
        bool more = (it + 1 < NIT);
        cp_wait<0>();
        __syncthreads();
        if (more) {
            cp_stage(cur ^ 1, (it + 1) * KC);
            sts_A(cur ^ 1);
        }
        if (it + 2 < NIT) load_A((it + 2) * KC);

        uint32_t abase = smem_a + (uint32_t)(cur * 64 * SW) * 4;
        uint32_t bbase = smem_b + (uint32_t)(cur * NN * SW) * 4;
#pragma unroll
        for (int kk = 0; kk < KC; kk += 8) {
            unsigned afr[MT][4];
#pragma unroll
            for (int mi = 0; mi < MT; mi++)
                ldsm4(afr[mi][0], afr[mi][1], afr[mi][2], afr[mi][3],
                      abase + (uint32_t)((wm * 32 + mi * 16 + ra) * SWB + kk * 4 + ca));
            unsigned bfr[8][2];
#pragma unroll
            for (int nis = 0; nis < 8; nis += 2)
                ldsm4(bfr[nis][0], bfr[nis][1], bfr[nis + 1][0], bfr[nis + 1][1],
                      bbase + (uint32_t)((wn * 64 + nis * 8 + rb) * SWB + kk * 4 + cb));
#pragma unroll
            for (int mi = 0; mi < MT; mi++)
#pragma unroll
                for (int ni = 0; ni < 8; ni++)
                    mma8(acc[mi][ni], afr[mi], bfr[ni]);
        }
    }

#pragma unroll
    for (int mi = 0; mi < MT; mi++)
#pragma unroll
        for (int ni = 0; ni < 8; ni++) {
            int col = wn * 64 + ni * 8 + q4 * 2;
            float b0 = __ldg(bias + n0 + col), b1v = __ldg(bias + n0 + col + 1);
#pragma unroll
            for (int h = 0; h < 2; h++) {
                int lr = wm * 32 + mi * 16 + gid + h * 8;
                *(float2*)(out + (size_t)(m0 + lr) * OSTRIDE + n0 + col) =
                    make_float2(acc[mi][ni][h * 2 + 0] + b0, acc[mi][ni][h * 2 + 1] + b1v);
            }
        }
}

// ---------------- alpha epilogue: per-row LN stats from [G|T], cos-sim -> alpha ----------------
__global__ void __launch_bounds__(256) alpha_epi_kernel(const float* __restrict__ GT,
                                                        const float* __restrict__ prompt,
                                                        float* __restrict__ alpha)
{
    extern __shared__ float dsm[];
    float* zs = dsm;             // [256 c][64 t] stride 65
    float* pnp = dsm + 256 * 65;
    int tid = threadIdx.x;
    int m0 = blockIdx.x * 64;
    int blk = m0 >> 10;
    const float* zb = g_z + (size_t)blk * (C_ * TOK_HF) + (m0 & 1023);
    for (int i = tid; i < 64 * 256; i += 256) {
        int c = i >> 6, t = i & 63;
        zs[c * 65 + t] = zb[(size_t)c * 1024 + t];
    }
    int warp = tid >> 5, lane = tid & 31;
    if (warp == 0) {
        float s = 0.f;
        for (int i = lane; i < 256; i += 32) { float v = __ldg(prompt + i); s += v * v; }
#pragma unroll
        for (int o = 16; o; o >>= 1) s += __shfl_xor_sync(0xffffffffu, s, o);
        if (lane == 0) pnp[0] = sqrtf(s);
    }
    __syncthreads();
    float pn = pnp[0];
    float b1s = g_sc[0], b1sq = g_sc[1];
#pragma unroll
    for (int rr = 0; rr < 8; rr++) {
        int r = warp * 8 + rr;
        int m = m0 + r;
        const float* Tr = GT + (size_t)m * 512 + 256;
        float tz = 0.f, zw = 0.f, zb2 = 0.f;
        for (int c = lane; c < 256; c += 32) {
            float z = zs[c * 65 + r];
            tz += __ldg(Tr + c) * z;
            zw += z * g_w1rs[c];
            zb2 += z * g_w1b1[c];
        }
#pragma unroll
        for (int o = 16; o; o >>= 1) {
            tz  += __shfl_xor_sync(0xffffffffu, tz, o);
            zw  += __shfl_xor_sync(0xffffffffu, zw, o);
            zb2 += __shfl_xor_sync(0xffffffffu, zb2, o);
        }
        float sum = zw + b1s;
        float sumsq = tz + 2.f * zb2 + b1sq;
        float mu = sum * (1.f / 512.f);
        float var = sumsq * (1.f / 512.f) - mu * mu;
        float rstd = rsqrtf(var + 1e-5f), murs = mu * rstd;
        const float* Gr = GT + (size_t)m * 512;
        float qp = 0.f, qq = 0.f;
        for (int c = lane; c < 256; c += 32) {
            float q = rstd * (__ldg(Gr + c) + g_bw2[c]) - murs * g_c1[c] + g_bp[c];
            qp += q * __ldg(prompt + c);
            qq += q * q;
        }
#pragma unroll
        for (int o = 16; o; o >>= 1) {
            qp += __shfl_xor_sync(0xffffffffu, qp, o);
            qq += __shfl_xor_sync(0xffffffffu, qq, o);
        }
        if (lane == 0) {
            float sim = qp / (fmaxf(sqrtf(qq), 1e-8f) * fmaxf(pn, 1e-8f));
            alpha[m] = fmaxf(sim, 0.f);
        }
    }
}

// ---------------- gate epilogue ----------------
__global__ void __launch_bounds__(256) gate_epi_kernel(const float* __restrict__ GTlf,
                                                       const float* __restrict__ ktok,
                                                       float* __restrict__ gate)
{
    int tid = threadIdx.x;
    int warp = tid >> 5, lane = tid & 31;
    int m0 = blockIdx.x * 64;
    float b1s = g_sc[2], b1sq = g_sc[3];
#pragma unroll
    for (int rr = 0; rr < 8; rr++) {
        int m = m0 + warp * 8 + rr;
        const float* kt = ktok + (size_t)m * 256;
        const float* Tr = GTlf + (size_t)m * 512 + 256;
        float tz = 0.f, zw = 0.f, zb2 = 0.f;
        for (int c = lane; c < 256; c += 32) {
            float z = __ldg(kt + c);
            tz += __ldg(Tr + c) * z;
            zw += z * g_w1rs[256 + c];
            zb2 += z * g_w1b1[256 + c];
        }
#pragma unroll
        for (int o = 16; o; o >>= 1) {
            tz  += __shfl_xor_sync(0xffffffffu, tz, o);
            zw  += __shfl_xor_sync(0xffffffffu, zw, o);
            zb2 += __shfl_xor_sync(0xffffffffu, zb2, o);
        }
        float sum = zw + b1s;
        float sumsq = tz + 2.f * zb2 + b1sq;
        float mu = sum * (1.f / 512.f);
        float var = sumsq * (1.f / 512.f) - mu * mu;
        float rstd = rsqrtf(var + 1e-5f), murs = mu * rstd;
        const float* Gr = GTlf + (size_t)m * 512;
        for (int c = lane; c < 256; c += 32) {
            float q = rstd * (__ldg(Gr + c) + g_bw2[256 + c]) - murs * g_c1[256 + c] + g_bp[256 + c];
            gate[(size_t)m * 256 + c] = 1.f / (1.f + expf(-q));
        }
    }
}

// ---------------- K5: apply alpha/gate, inverse Haar, write output ----------------
__global__ void final_kernel(const float* __restrict__ xb, float* __restrict__ out)
{
    __shared__ __align__(16) float xs[8 * 128];
    int bi = blockIdx.x, c = blockIdx.y, b = blockIdx.z;
    size_t img = ((size_t)(b * C_ + c)) * H_;
    int t = threadIdx.x;
    int lrow = t >> 5, lcol = t & 31;
    ((float4*)xs)[t] = ((const float4*)(xb + (img + 8 * bi + lrow) * W_))[lcol];
    __syncthreads();
    int rp = t >> 6, j = t & 63;
    float2 top = ((const float2*)(xs + (2 * rp) * W_))[j];
    float2 bot = ((const float2*)(xs + (2 * rp + 1) * W_))[j];
    float p00 = top.x, p01 = top.y, p10 = bot.x, p11 = bot.y;
    float a  = 0.25f * (p00 + p01 + p10 + p11);
    float hb = 0.25f * (p00 - p01 + p10 - p11);
    float vb = 0.25f * (p00 + p01 - p10 - p11);
    float db = 0.25f * (p00 - p01 - p10 + p11);
    int hr = 4 * bi + rp, hc = j;
    int tok = (hr >> 1) * 32 + (hc >> 1);
    float ah = __ldg(&g_alpha[(0 * B_ + b) * TOK_HF + tok]);
    float av = __ldg(&g_alpha[(1 * B_ + b) * TOK_HF + tok]);
    float ad = __ldg(&g_alpha[(2 * B_ + b) * TOK_HF + tok]);
    int tg = (hr >> 2) * 16 + (hc >> 2);
    float gt = __ldg(&g_gate[((size_t)(b * 256 + tg)) * C_ + c]);
    float ae = a * gt, he = hb * ah, ve = vb * av, de = db * ad;
    float2 o0 = make_float2(ae + he + ve + de, ae - he + ve - de);
    float2 o1 = make_float2(ae + he - ve - de, ae - he - ve + de);
    int row0 = 8 * bi + 2 * rp;
    ((float2*)(out + (img + row0) * W_))[j] = o0;
    ((float2*)(out + (img + row0 + 1) * W_))[j] = o1;
}

static constexpr int SMEM_G = (2 * 64 * 36 + 2 * 256 * 36) * 4 + 64;
static constexpr int SMEM_AE = (256 * 65 + 4) * 4;

extern "C" void kernel_launch(void* const* d_in, const int* in_sizes, int n_in,
                              void* d_out, int out_size)
{
    const float* xb      = (const float*)d_in[0];
    const float* xsm     = (const float*)d_in[1];
    const float* hf_w1   = (const float*)d_in[2];
    const float* hf_b1   = (const float*)d_in[3];
    const float* hf_ln_w = (const float*)d_in[4];
    const float* hf_ln_b = (const float*)d_in[5];
    const float* hf_w2   = (const float*)d_in[6];
    const float* hf_b2   = (const float*)d_in[7];
    const float* hf_pr   = (const float*)d_in[8];
    const float* low_w   = (const float*)d_in[9];
    const float* low_b   = (const float*)d_in[10];
    const float* lf_w1   = (const float*)d_in[11];
    const float* lf_b1   = (const float*)d_in[12];
    const float* lf_ln_w = (const float*)d_in[13];
    const float* lf_ln_b = (const float*)d_in[14];
    const float* lf_w2   = (const float*)d_in[15];
    const float* lf_b2   = (const float*)d_in[16];

    void *pz, *pps, *pGT, *pGTlf, *pktok, *pgate, *palpha, *pwt, *pBT, *pzero;
    cudaGetSymbolAddress(&pz, g_z);
    cudaGetSymbolAddress(&pps, g_ps);
    cudaGetSymbolAddress(&pGT, g_GT);
    cudaGetSymbolAddress(&pGTlf, g_GTlf);
    cudaGetSymbolAddress(&pktok, g_ktok);
    cudaGetSymbolAddress(&pgate, g_gate);
    cudaGetSymbolAddress(&palpha, g_alpha);
    cudaGetSymbolAddress(&pwt, g_wt);
    cudaGetSymbolAddress(&pBT, g_BT);
    cudaGetSymbolAddress(&pzero, g_zero);
    const float* wt = (const float*)pwt;
    const float* BT = (const float*)pBT;
    const float* zero = (const float*)pzero;

    cudaFuncSetAttribute((const void*)gemm256_kernel<256, 0, 512>,
                         cudaFuncAttributeMaxDynamicSharedMemorySize, SMEM_G);
    cudaFuncSetAttribute((const void*)gemm256_kernel<512, 1, 256>,
                         cudaFuncAttributeMaxDynamicSharedMemorySize, SMEM_G);
    cudaFuncSetAttribute((const void*)gemm256_kernel<256, 2, 512>,
                         cudaFuncAttributeMaxDynamicSharedMemorySize, SMEM_G);
    cudaFuncSetAttribute((const void*)alpha_epi_kernel,
                         cudaFuncAttributeMaxDynamicSharedMemorySize, SMEM_AE);

    transpose5_kernel<<<dim3(16, 16, 5), dim3(32, 8)>>>(hf_w1, hf_w2, low_w, lf_w1, lf_w2,
                                                        hf_ln_w, lf_ln_w);
    fold_kernel<<<2, 256>>>(hf_w2, hf_ln_b, hf_b2, hf_b1, lf_w2, lf_ln_b, lf_b2, lf_b1);
    fold2_kernel<<<2, 256>>>(hf_w1, hf_b1, lf_w1, lf_b1);
    prep_dot_kernel<<<dim3(512, 2), 128>>>(hf_w1, lf_w1);
    haar_z_kernel<<<dim3(4, 256, 16), 256>>>(xb);
    pool_small_kernel<<<dim3(512, 16), 256>>>(xsm);

    // hf: one GEMM [G|T] = z @ [W12|Q]^T, then alpha epilogue
    gemm256_kernel<256, 0, 512><<<dim3(M_HF / 64, 2), 256, SMEM_G>>>(
        (const float*)pz, BT, zero, (float*)pGT);
    alpha_epi_kernel<<<M_HF / 64, 256, SMEM_AE>>>((const float*)pGT, hf_pr, (float*)palpha);

    // lf: ktok GEMM, then [G|T] GEMM, then gate epilogue
    gemm256_kernel<512, 1, 256><<<dim3(M_LF / 64, 1), 256, SMEM_G>>>(
        (const float*)pps, wt + 2 * 512 * 256, low_b, (float*)pktok);
    gemm256_kernel<256, 2, 512><<<dim3(M_LF / 64, 2), 256, SMEM_G>>>(
        (const float*)pktok, BT + 512 * 256, zero, (float*)pGTlf);
    gate_epi_kernel<<<M_LF / 64, 256>>>((const float*)pGTlf, (const float*)pktok, (float*)pgate);

    final_kernel<<<dim3(16, 256, 16), 256>>>(xb, (float*)d_out);
}

// round 10
// speedup vs baseline: 1.5894x; 1.5894x over previous
#include <cuda_runtime.h>
#include <cuda_bf16.h>
#include <cstdint>
#include <math.h>

#define DEV_INLINE __device__ __forceinline__

static constexpr int B_ = 16, C_ = 256, H_ = 128, W_ = 128;
static constexpr int CS = 512;
static constexpr int TOK_HF = 1024;
static constexpr int M_HF = 3 * B_ * TOK_HF;     // 49152
static constexpr int M_LF = B_ * 256;            // 4096

// ---------------- scratch ----------------
__device__ __nv_bfloat16 g_z[3ULL * B_ * C_ * TOK_HF];   // [band][b][c][tok] bf16
__device__ float g_ps[(size_t)B_ * CS * 256];            // [b][s][tok]
__device__ __nv_bfloat16 g_Hh[(size_t)M_HF * 512];       // RAW hidden (hf) bf16
__device__ float g_Hlf[(size_t)M_LF * 512];              // RAW hidden (lf) fp32
__device__ float g_ktok[(size_t)M_LF * C_];
__device__ float g_gate[(size_t)M_LF * C_];
__device__ float g_alpha[3 * B_ * TOK_HF];
__device__ float g_wt[5ULL * 512 * 256];                 // transposed weights [n][k] fp32
__device__ __nv_bfloat16 g_wth[2ULL * 512 * 256];        // bf16: [0]=hf_w1t(512n,256k), [1]=hf_w2t'(256n,512k)
__device__ float2 g_stats_hf[(size_t)M_HF * 2];
__device__ float2 g_stats_lf[(size_t)M_LF * 2];
__device__ float g_c1[2 * 256];
__device__ float g_bp[2 * 256];

// ---------------- weight transpose (+ LN-weight folding + bf16 copies) ----------------
__global__ void transpose5_kernel(const float* __restrict__ w0, const float* __restrict__ w1,
                                  const float* __restrict__ w2, const float* __restrict__ w3,
                                  const float* __restrict__ w4,
                                  const float* __restrict__ hf_lnw, const float* __restrict__ lf_lnw)
{
    __shared__ float tile[32][33];
    int mi = blockIdx.z;
    const float* in; int R, Cc; const float* lnw = nullptr;
    switch (mi) {
        case 0: in = w0; R = 256; Cc = 512; break;                 // hf_w1 -> [512n][256k]
        case 1: in = w1; R = 512; Cc = 256; lnw = hf_lnw; break;   // hf_w2' -> [256n][512k]
        case 2: in = w2; R = 512; Cc = 256; break;
        case 3: in = w3; R = 256; Cc = 512; break;
        default: in = w4; R = 512; Cc = 256; lnw = lf_lnw; break;
    }
    float* out = g_wt + (size_t)mi * 512 * 256;
    int bx = blockIdx.x * 32, by = blockIdx.y * 32;
    if (bx >= Cc || by >= R) return;
    int tx = threadIdx.x, ty = threadIdx.y;
#pragma unroll
    for (int j = 0; j < 32; j += 8) {
        int row = by + ty + j;
        float v = in[(size_t)row * Cc + bx + tx];
        if (lnw) v *= __ldg(lnw + row);
        tile[ty + j][tx] = v;
    }
    __syncthreads();
#pragma unroll
    for (int j = 0; j < 32; j += 8) {
        float v = tile[tx][ty + j];
        size_t oidx = (size_t)(bx + ty + j) * R + by + tx;
        out[oidx] = v;
        if (mi == 0) g_wth[oidx] = __float2bfloat16(v);
        if (mi == 1) g_wth[512 * 256 + oidx] = __float2bfloat16(v);
    }
}

// fold: c1[n]=col-sums of W2'; bp[n]=b2[n]+lnb@W2
__global__ void fold_kernel(const float* __restrict__ w2a, const float* __restrict__ lnba,
                            const float* __restrict__ b2a,
                            const float* __restrict__ w2b, const float* __restrict__ lnbb,
                            const float* __restrict__ b2b)
{
    int mi = blockIdx.x;
    int n = threadIdx.x;
    const float* wt = g_wt + (size_t)(mi ? 4 : 1) * 512 * 256;
    const float* w2 = mi ? w2b : w2a;
    const float* lnb = mi ? lnbb : lnba;
    const float* b2 = mi ? b2b : b2a;
    float s1 = 0.f, s2 = 0.f;
    for (int k = 0; k < 512; k++) {
        s1 += wt[(size_t)n * 512 + k];
        s2 += lnb[k] * w2[(size_t)k * 256 + n];
    }
    g_c1[mi * 256 + n] = s1;
    g_bp[mi * 256 + n] = b2[n] + s2;
}

// ---------------- K1: Haar bands -> abs-pooled z tokens (bf16 out) ----------------
__global__ void haar_z_kernel(const float* __restrict__ xb)
{
    int tid = threadIdx.x;
    int tk = blockIdx.x * 256 + tid;
    int c = blockIdx.y, b = blockIdx.z;
    int ti = tk >> 5, tj = tk & 31;
    const float* base = xb + ((size_t)(b * C_ + c) * H_ + 4 * ti) * W_ + 4 * tj;
    float4 r0 = *(const float4*)(base);
    float4 r1 = *(const float4*)(base + W_);
    float4 r2 = *(const float4*)(base + 2 * W_);
    float4 r3 = *(const float4*)(base + 3 * W_);
    float zh = 0.f, zv = 0.f, zd = 0.f;
#define HBLK(p00, p01, p10, p11) \
    zh += fabsf((p00) - (p01) + (p10) - (p11)); \
    zv += fabsf((p00) + (p01) - (p10) - (p11)); \
    zd += fabsf((p00) - (p01) - (p10) + (p11));
    HBLK(r0.x, r0.y, r1.x, r1.y)
    HBLK(r0.z, r0.w, r1.z, r1.w)
    HBLK(r2.x, r2.y, r3.x, r3.y)
    HBLK(r2.z, r2.w, r3.z, r3.w)
#undef HBLK
    const float s = 0.0625f;
    size_t base_o = ((size_t)(b) * C_ + c) * TOK_HF + tk;
    const size_t BS = (size_t)B_ * C_ * TOK_HF;
    g_z[base_o]          = __float2bfloat16(zh * s);
    g_z[BS + base_o]     = __float2bfloat16(zv * s);
    g_z[2 * BS + base_o] = __float2bfloat16(zd * s);
}

// ---------------- K2: 4x4 mean-pool of x_small ----------------
__global__ void pool_small_kernel(const float* __restrict__ xsm)
{
    int s = blockIdx.x, b = blockIdx.y;
    const float* src = xsm + ((size_t)(b * CS + s)) * 64 * 64;
    int t = threadIdx.x;
    int tj = t & 15, ti = t >> 4;
    float sum = 0.f;
#pragma unroll
    for (int r = 0; r < 4; r++) {
        float4 v = *(const float4*)(src + (4 * ti + r) * 64 + 4 * tj);
        sum += v.x + v.y + v.z + v.w;
    }
    g_ps[((size_t)(b * CS + s)) * 256 + t] = sum * (1.f / 16.f);
}

// ---------------- asm helpers ----------------
DEV_INLINE void mma8(float* c, const unsigned* a, const unsigned* b) {
    asm volatile("mma.sync.aligned.m16n8k8.row.col.f32.tf32.tf32.f32 "
                 "{%0,%1,%2,%3}, {%4,%5,%6,%7}, {%8,%9}, {%0,%1,%2,%3};"
                 : "+f"(c[0]), "+f"(c[1]), "+f"(c[2]), "+f"(c[3])
                 : "r"(a[0]), "r"(a[1]), "r"(a[2]), "r"(a[3]),
                   "r"(b[0]), "r"(b[1]));
}
DEV_INLINE void mma16(float* c, const unsigned* a, const unsigned* b) {
    asm volatile("mma.sync.aligned.m16n8k16.row.col.f32.bf16.bf16.f32 "
                 "{%0,%1,%2,%3}, {%4,%5,%6,%7}, {%8,%9}, {%0,%1,%2,%3};"
                 : "+f"(c[0]), "+f"(c[1]), "+f"(c[2]), "+f"(c[3])
                 : "r"(a[0]), "r"(a[1]), "r"(a[2]), "r"(a[3]),
                   "r"(b[0]), "r"(b[1]));
}
DEV_INLINE void ldsm4(unsigned& r0, unsigned& r1, unsigned& r2, unsigned& r3, uint32_t addr) {
    asm volatile("ldmatrix.sync.aligned.m8n8.x4.shared.b16 {%0,%1,%2,%3}, [%4];"
                 : "=r"(r0), "=r"(r1), "=r"(r2), "=r"(r3) : "r"(addr));
}
DEV_INLINE void cp16(uint32_t s, const void* g) {
    asm volatile("cp.async.cg.shared.global [%0], [%1], 16;" :: "r"(s), "l"(g));
}
DEV_INLINE void cp_commit() { asm volatile("cp.async.commit_group;"); }
template<int NN> DEV_INLINE void cp_wait() { asm volatile("cp.async.wait_group %0;" :: "n"(NN)); }

// ---------------- tf32 64x256-tile GEMM (R6-proven, lf chain) ----------------
template<int K, int AMODE, int EPI, int OSTRIDE>
__global__ void __launch_bounds__(256, 2)
gemm256_kernel(const float* __restrict__ A, const float* __restrict__ Bt,
               const float* __restrict__ bias, const float* __restrict__ p0,
               float* __restrict__ out, float2* __restrict__ stats,
               const float* __restrict__ c1)
{
    constexpr int KC = 32, SW = 36, SWB = SW * 4, NIT = K / KC, NN = 256;
    constexpr int MT = 2;

    extern __shared__ __align__(16) float dsm[];
    float* As = dsm;
    float* Bs = As + 2 * 64 * SW;
    float* sred = Bs + 2 * NN * SW;
    float* ssred = sred + 256;

    int tid = threadIdx.x;
    int lane = tid & 31, warp = tid >> 5;
    int wn = warp & 3, wm = warp >> 2;
    int gid = lane >> 2, q4 = lane & 3;
    int m0 = blockIdx.x * 64;
    int n0 = blockIdx.y * 256;

    const float* Ab; int astride = 0;
    if (AMODE == 1) { Ab = A + (size_t)(m0 >> 8) * (CS * 256) + (m0 & 255); astride = 256; }
    else { Ab = A + (size_t)m0 * K; }
    const float* BtB = Bt + (size_t)n0 * K;

    uint32_t smem_a = (uint32_t)__cvta_generic_to_shared(As);
    uint32_t smem_b = (uint32_t)__cvta_generic_to_shared(Bs);

    int la_m = tid & 63, la_kg = tid >> 6;
    float areg[8];
    auto load_A = [&](int k0) {
        if (AMODE == 1) {
#pragma unroll
            for (int i = 0; i < 8; i++)
                areg[i] = __ldg(Ab + (size_t)(k0 + la_kg * 8 + i) * astride + la_m);
        }
    };
    auto sts_A = [&](int st) {
        if (AMODE == 1) {
            float* p = As + st * 64 * SW + la_m * SW + la_kg * 8;
            *(float4*)(p)     = make_float4(areg[0], areg[1], areg[2], areg[3]);
            *(float4*)(p + 4) = make_float4(areg[4], areg[5], areg[6], areg[7]);
        }
    };
    auto cp_stage = [&](int st, int k0) {
        if (AMODE == 2) {
#pragma unroll
            for (int j = 0; j < 2; j++) {
                int idx = tid + j * 256;
                int m = idx >> 3, kq = idx & 7;
                cp16(smem_a + (uint32_t)((st * 64 + m) * SW + kq * 4) * 4,
                     Ab + (size_t)m * K + k0 + kq * 4);
            }
        }
#pragma unroll
        for (int j = 0; j < 8; j++) {
            int idx = tid + j * 256;
            int n = idx >> 3, kc = idx & 7;
            cp16(smem_b + (uint32_t)((st * NN + n) * SW + kc * 4) * 4,
                 BtB + (size_t)n * K + k0 + kc * 4);
        }
        cp_commit();
    };

    int ra = lane & 15;
    int ca = (lane & 16) ? 16 : 0;
    int rb = (lane & 7) + ((lane >> 4) << 3);
    int cb = (lane & 8) ? 16 : 0;

    float acc[MT][8][4];
#pragma unroll
    for (int mi = 0; mi < MT; mi++)
#pragma unroll
        for (int ni = 0; ni < 8; ni++)
#pragma unroll
            for (int e = 0; e < 4; e++) acc[mi][ni][e] = 0.f;

    load_A(0);
    cp_stage(0, 0);
    sts_A(0);
    if (NIT > 1) load_A(KC);

    for (int it = 0; it < NIT; it++) {
        int cur = it & 1;
        bool more = (it + 1 < NIT);
        cp_wait<0>();
        __syncthreads();
        if (more) {
            cp_stage(cur ^ 1, (it + 1) * KC);
            sts_A(cur ^ 1);
        }
        if (it + 2 < NIT) load_A((it + 2) * KC);

        uint32_t abase = smem_a + (uint32_t)(cur * 64 * SW) * 4;
        uint32_t bbase = smem_b + (uint32_t)(cur * NN * SW) * 4;
#pragma unroll
        for (int kk = 0; kk < KC; kk += 8) {
            unsigned afr[MT][4];
#pragma unroll
            for (int mi = 0; mi < MT; mi++)
                ldsm4(afr[mi][0], afr[mi][1], afr[mi][2], afr[mi][3],
                      abase + (uint32_t)((wm * 32 + mi * 16 + ra) * SWB + kk * 4 + ca));
            unsigned bfr[8][2];
#pragma unroll
            for (int nis = 0; nis < 8; nis += 2)
                ldsm4(bfr[nis][0], bfr[nis][1], bfr[nis + 1][0], bfr[nis + 1][1],
                      bbase + (uint32_t)((wn * 64 + nis * 8 + rb) * SWB + kk * 4 + cb));
#pragma unroll
            for (int mi = 0; mi < MT; mi++)
#pragma unroll
                for (int ni = 0; ni < 8; ni++)
                    mma8(acc[mi][ni], afr[mi], bfr[ni]);
        }
    }

    float mu_rs[MT][2], rstd_v[MT][2];
    if (EPI == 3) {
#pragma unroll
        for (int mi = 0; mi < MT; mi++)
#pragma unroll
            for (int h = 0; h < 2; h++) {
                int lr = wm * 32 + mi * 16 + gid + h * 8;
                float2 s0 = stats[(size_t)(m0 + lr) * 2 + 0];
                float2 s1 = stats[(size_t)(m0 + lr) * 2 + 1];
                float sum = s0.x + s1.x, ss = s0.y + s1.y;
                float mu = sum * (1.f / 512.f);
                float var = ss * (1.f / 512.f) - mu * mu;
                float rstd = rsqrtf(var + 1e-5f);
                rstd_v[mi][h] = rstd;
                mu_rs[mi][h] = mu * rstd;
            }
    }

    float rs[MT][2], rss[MT][2];
#pragma unroll
    for (int mi = 0; mi < MT; mi++) { rs[mi][0] = rs[mi][1] = 0.f; rss[mi][0] = rss[mi][1] = 0.f; }

#pragma unroll
    for (int mi = 0; mi < MT; mi++)
#pragma unroll
        for (int ni = 0; ni < 8; ni++)
#pragma unroll
            for (int e4 = 0; e4 < 4; e4++) {
                int h = e4 >> 1, e = e4 & 1;
                int col = wn * 64 + ni * 8 + q4 * 2 + e;
                float v;
                if (EPI <= 1) {
                    v = acc[mi][ni][e4] + __ldg(bias + n0 + col);
                    if (EPI == 1) { rs[mi][h] += v; rss[mi][h] += v * v; }
                } else {
                    v = rstd_v[mi][h] * acc[mi][ni][e4] - mu_rs[mi][h] * __ldg(c1 + col)
                        + __ldg(bias + col);
                }
                acc[mi][ni][e4] = v;
            }

    if (EPI == 1) {
#pragma unroll
        for (int mi = 0; mi < MT; mi++)
#pragma unroll
            for (int h = 0; h < 2; h++) {
                float s = rs[mi][h], ss = rss[mi][h];
                s  += __shfl_xor_sync(0xffffffffu, s, 1);
                s  += __shfl_xor_sync(0xffffffffu, s, 2);
                ss += __shfl_xor_sync(0xffffffffu, ss, 1);
                ss += __shfl_xor_sync(0xffffffffu, ss, 2);
                if (q4 == 0) {
                    int lr = wm * 32 + mi * 16 + gid + h * 8;
                    sred[lr * 4 + wn] = s; ssred[lr * 4 + wn] = ss;
                }
            }
        __syncthreads();
    }

#pragma unroll
    for (int mi = 0; mi < MT; mi++)
#pragma unroll
        for (int ni = 0; ni < 8; ni++) {
            int col = wn * 64 + ni * 8 + q4 * 2;
#pragma unroll
            for (int h = 0; h < 2; h++) {
                int lr = wm * 32 + mi * 16 + gid + h * 8;
                float vx = acc[mi][ni][h * 2 + 0], vy = acc[mi][ni][h * 2 + 1];
                if (EPI == 3) { vx = 1.f / (1.f + expf(-vx)); vy = 1.f / (1.f + expf(-vy)); }
                *(float2*)(out + (size_t)(m0 + lr) * OSTRIDE + n0 + col) = make_float2(vx, vy);
            }
        }
    if (EPI == 1) {
        if (tid < 64) {
            float s = 0.f, ss = 0.f;
#pragma unroll
            for (int j = 0; j < 4; j++) { s += sred[tid * 4 + j]; ss += ssred[tid * 4 + j]; }
            stats[(size_t)(m0 + tid) * 2 + blockIdx.y] = make_float2(s, ss);
        }
    }
}

// ---------------- bf16 64x256-tile GEMM (hf chain) ----------------
// AMODE: 0 = z-layout bf16 ([blk][k][1024]); 2 = row-major bf16.
// EPI: 1 = +bias, store bf16 H + partial stats; 2 = LN-fold + cos-sim -> relu alpha.
template<int K, int AMODE, int EPI, int OSTRIDE>
__global__ void __launch_bounds__(256, 2)
gemmh_kernel(const __nv_bfloat16* __restrict__ A, const __nv_bfloat16* __restrict__ Bt,
             const float* __restrict__ bias, const float* __restrict__ p0,
             void* __restrict__ outv, float2* __restrict__ stats,
             const float* __restrict__ c1)
{
    constexpr int KC = 32, SW = 40 /*halves*/, SWB = SW * 2 /*bytes=80*/, NIT = K / KC, NN = 256;
    constexpr int MT = 2;

    extern __shared__ __align__(16) char dsmh[];
    __nv_bfloat16* As = (__nv_bfloat16*)dsmh;            // 2*64*40 halves
    __nv_bfloat16* Bs = As + 2 * 64 * SW;                // 2*256*40 halves
    float* sred = (float*)(Bs + 2 * NN * SW);
    float* ssred = sred + 256;
    float* spn = ssred + 256;

    int tid = threadIdx.x;
    int lane = tid & 31, warp = tid >> 5;
    int wn = warp & 3, wm = warp >> 2;
    int gid = lane >> 2, q4 = lane & 3;
    int m0 = blockIdx.x * 64;
    int n0 = blockIdx.y * 256;

    const __nv_bfloat16* Ab; int astride = 0;
    if (AMODE == 0) { Ab = A + (size_t)(m0 >> 10) * (C_ * TOK_HF) + (m0 & 1023); astride = TOK_HF; }
    else { Ab = A + (size_t)m0 * K; }
    const __nv_bfloat16* BtB = Bt + (size_t)n0 * K;

    if (EPI == 2 && warp == 0) {
        float s = 0.f;
        for (int i = lane; i < 256; i += 32) { float v = __ldg(p0 + i); s += v * v; }
#pragma unroll
        for (int o = 16; o; o >>= 1) s += __shfl_xor_sync(0xffffffffu, s, o);
        if (lane == 0) *spn = sqrtf(s);
    }

    uint32_t smem_a = (uint32_t)__cvta_generic_to_shared(As);
    uint32_t smem_b = (uint32_t)__cvta_generic_to_shared(Bs);

    int la_m = tid & 63, la_kg = tid >> 6;     // 4 k-groups of 8
    unsigned areg[4];                           // 8 halves packed
    auto load_A = [&](int k0) {
        if (AMODE == 0) {
            const unsigned short* Au = (const unsigned short*)Ab;
            unsigned short h[8];
#pragma unroll
            for (int i = 0; i < 8; i++)
                h[i] = __ldg(Au + (size_t)(k0 + la_kg * 8 + i) * astride + la_m);
#pragma unroll
            for (int j = 0; j < 4; j++)
                areg[j] = (unsigned)h[2 * j] | ((unsigned)h[2 * j + 1] << 16);
        }
    };
    auto sts_A = [&](int st) {
        if (AMODE == 0)
            *(uint4*)(As + (size_t)(st * 64 + la_m) * SW + la_kg * 8) =
                make_uint4(areg[0], areg[1], areg[2], areg[3]);
    };
    auto cp_stage = [&](int st, int k0) {
        if (AMODE == 2) {
            int m = tid >> 2, kq = tid & 3;    // 64 m x 4 chunks of 8 halves
            cp16(smem_a + (uint32_t)((st * 64 + m) * SW + kq * 8) * 2,
                 Ab + (size_t)m * K + k0 + kq * 8);
        }
#pragma unroll
        for (int j = 0; j < 4; j++) {          // 256 n x 4 chunks
            int idx = tid + j * 256;
            int n = idx >> 2, kc = idx & 3;
            cp16(smem_b + (uint32_t)((st * NN + n) * SW + kc * 8) * 2,
                 BtB + (size_t)n * K + k0 + kc * 8);
        }
        cp_commit();
    };

    int ra = lane & 15;
    int ca = (lane >> 4) * 16;                  // byte offset: second 8 k-halves
    int rb = (lane & 7) + ((lane >> 4) << 3);
    int cb = (lane & 8) ? 16 : 0;

    float acc[MT][8][4];
#pragma unroll
    for (int mi = 0; mi < MT; mi++)
#pragma unroll
        for (int ni = 0; ni < 8; ni++)
#pragma unroll
            for (int e = 0; e < 4; e++) acc[mi][ni][e] = 0.f;

    load_A(0);
    cp_stage(0, 0);
    sts_A(0);
    if (NIT > 1) load_A(KC);

    for (int it = 0; it < NIT; it++) {
        int cur = it & 1;
        bool more = (it + 1 < NIT);
        cp_wait<0>();
        __syncthreads();
        if (more) {
            cp_stage(cur ^ 1, (it + 1) * KC);
            sts_A(cur ^ 1);
        }
        if (it + 2 < NIT) load_A((it + 2) * KC);

        uint32_t abase = smem_a + (uint32_t)(cur * 64 * SW) * 2;
        uint32_t bbase = smem_b + (uint32_t)(cur * NN * SW) * 2;
#pragma unroll
        for (int kk = 0; kk < 2; kk++) {        // two k16 steps
            unsigned afr[MT][4];
#pragma unroll
            for (int mi = 0; mi < MT; mi++)
                ldsm4(afr[mi][0], afr[mi][1], afr[mi][2], afr[mi][3],
                      abase + (uint32_t)((wm * 32 + mi * 16 + ra) * SWB + ca + kk * 32));
            unsigned bfr[8][2];
#pragma unroll
            for (int nis = 0; nis < 8; nis += 2)
                ldsm4(bfr[nis][0], bfr[nis][1], bfr[nis + 1][0], bfr[nis + 1][1],
                      bbase + (uint32_t)((wn * 64 + nis * 8 + rb) * SWB + cb + kk * 32));
#pragma unroll
            for (int mi = 0; mi < MT; mi++)
#pragma unroll
                for (int ni = 0; ni < 8; ni++)
                    mma16(acc[mi][ni], afr[mi], bfr[ni]);
        }
    }

    // ---- epilogue ----
    float mu_rs[MT][2], rstd_v[MT][2];
    if (EPI == 2) {
#pragma unroll
        for (int mi = 0; mi < MT; mi++)
#pragma unroll
            for (int h = 0; h < 2; h++) {
                int lr = wm * 32 + mi * 16 + gid + h * 8;
                float2 s0 = stats[(size_t)(m0 + lr) * 2 + 0];
                float2 s1 = stats[(size_t)(m0 + lr) * 2 + 1];
                float sum = s0.x + s1.x, ss = s0.y + s1.y;
                float mu = sum * (1.f / 512.f);
                float var = ss * (1.f / 512.f) - mu * mu;
                float rstd = rsqrtf(var + 1e-5f);
                rstd_v[mi][h] = rstd;
                mu_rs[mi][h] = mu * rstd;
            }
    }

    float rs[MT][2], rss[MT][2];
#pragma unroll
    for (int mi = 0; mi < MT; mi++) { rs[mi][0] = rs[mi][1] = 0.f; rss[mi][0] = rss[mi][1] = 0.f; }

#pragma unroll
    for (int mi = 0; mi < MT; mi++)
#pragma unroll
        for (int ni = 0; ni < 8; ni++)
#pragma unroll
            for (int e4 = 0; e4 < 4; e4++) {
                int h = e4 >> 1, e = e4 & 1;
                int col = wn * 64 + ni * 8 + q4 * 2 + e;
                float v;
                if (EPI == 1) {
                    v = acc[mi][ni][e4] + __ldg(bias + n0 + col);
                    rs[mi][h] += v; rss[mi][h] += v * v;
                } else {
                    v = rstd_v[mi][h] * acc[mi][ni][e4] - mu_rs[mi][h] * __ldg(c1 + col)
                        + __ldg(bias + col);
                    rs[mi][h] += v * __ldg(p0 + col); rss[mi][h] += v * v;
                }
                acc[mi][ni][e4] = v;
            }

#pragma unroll
    for (int mi = 0; mi < MT; mi++)
#pragma unroll
        for (int h = 0; h < 2; h++) {
            float s = rs[mi][h], ss = rss[mi][h];
            s  += __shfl_xor_sync(0xffffffffu, s, 1);
            s  += __shfl_xor_sync(0xffffffffu, s, 2);
            ss += __shfl_xor_sync(0xffffffffu, ss, 1);
            ss += __shfl_xor_sync(0xffffffffu, ss, 2);
            if (q4 == 0) {
                int lr = wm * 32 + mi * 16 + gid + h * 8;
                sred[lr * 4 + wn] = s; ssred[lr * 4 + wn] = ss;
            }
        }
    __syncthreads();

    if (EPI == 1) {
        __nv_bfloat16* outp = (__nv_bfloat16*)outv;
#pragma unroll
        for (int mi = 0; mi < MT; mi++)
#pragma unroll
            for (int ni = 0; ni < 8; ni++) {
                int col = wn * 64 + ni * 8 + q4 * 2;
#pragma unroll
                for (int h = 0; h < 2; h++) {
                    int lr = wm * 32 + mi * 16 + gid + h * 8;
                    *(__nv_bfloat162*)(outp + (size_t)(m0 + lr) * OSTRIDE + n0 + col) =
                        __floats2bfloat162_rn(acc[mi][ni][h * 2 + 0], acc[mi][ni][h * 2 + 1]);
                }
            }
        if (tid < 64) {
            float s = 0.f, ss = 0.f;
#pragma unroll
            for (int j = 0; j < 4; j++) { s += sred[tid * 4 + j]; ss += ssred[tid * 4 + j]; }
            stats[(size_t)(m0 + tid) * 2 + blockIdx.y] = make_float2(s, ss);
        }
    }
    if (EPI == 2) {
        if (tid < 64) {
            float dot = 0.f, nsq = 0.f;
#pragma unroll
            for (int j = 0; j < 4; j++) { dot += sred[tid * 4 + j]; nsq += ssred[tid * 4 + j]; }
            float nq = sqrtf(nsq);
            float sim = dot / (fmaxf(nq, 1e-8f) * fmaxf(*spn, 1e-8f));
            ((float*)outv)[m0 + tid] = fmaxf(sim, 0.f);
        }
    }
}

// ---------------- K5: apply alpha/gate, inverse Haar, write output ----------------
__global__ void final_kernel(const float* __restrict__ xb, float* __restrict__ out)
{
    __shared__ __align__(16) float xs[8 * 128];
    int bi = blockIdx.x, c = blockIdx.y, b = blockIdx.z;
    size_t img = ((size_t)(b * C_ + c)) * H_;
    int t = threadIdx.x;
    int lrow = t >> 5, lcol = t & 31;
    ((float4*)xs)[t] = ((const float4*)(xb + (img + 8 * bi + lrow) * W_))[lcol];
    __syncthreads();
    int rp = t >> 6, j = t & 63;
    float2 top = ((const float2*)(xs + (2 * rp) * W_))[j];
    float2 bot = ((const float2*)(xs + (2 * rp + 1) * W_))[j];
    float p00 = top.x, p01 = top.y, p10 = bot.x, p11 = bot.y;
    float a  = 0.25f * (p00 + p01 + p10 + p11);
    float hb = 0.25f * (p00 - p01 + p10 - p11);
    float vb = 0.25f * (p00 + p01 - p10 - p11);
    float db = 0.25f * (p00 - p01 - p10 + p11);
    int hr = 4 * bi + rp, hc = j;
    int tok = (hr >> 1) * 32 + (hc >> 1);
    float ah = __ldg(&g_alpha[(0 * B_ + b) * TOK_HF + tok]);
    float av = __ldg(&g_alpha[(1 * B_ + b) * TOK_HF + tok]);
    float ad = __ldg(&g_alpha[(2 * B_ + b) * TOK_HF + tok]);
    int tg = (hr >> 2) * 16 + (hc >> 2);
    float gt = __ldg(&g_gate[((size_t)(b * 256 + tg)) * C_ + c]);
    float ae = a * gt, he = hb * ah, ve = vb * av, de = db * ad;
    float2 o0 = make_float2(ae + he + ve + de, ae - he + ve - de);
    float2 o1 = make_float2(ae + he - ve - de, ae - he - ve + de);
    int row0 = 8 * bi + 2 * rp;
    ((float2*)(out + (img + row0) * W_))[j] = o0;
    ((float2*)(out + (img + row0 + 1) * W_))[j] = o1;
}

static constexpr int SMEM_G = (2 * 64 * 36 + 2 * 256 * 36 + 512 + 4) * 4;       // ~92 KB
static constexpr int SMEM_H = (2 * 64 * 40 + 2 * 256 * 40) * 2 + (512 + 4) * 4; // ~53 KB

extern "C" void kernel_launch(void* const* d_in, const int* in_sizes, int n_in,
                              void* d_out, int out_size)
{
    const float* xb      = (const float*)d_in[0];
    const float* xsm     = (const float*)d_in[1];
    const float* hf_w1   = (const float*)d_in[2];
    const float* hf_b1   = (const float*)d_in[3];
    const float* hf_ln_w = (const float*)d_in[4];
    const float* hf_ln_b = (const float*)d_in[5];
    const float* hf_w2   = (const float*)d_in[6];
    const float* hf_b2   = (const float*)d_in[7];
    const float* hf_pr   = (const float*)d_in[8];
    const float* low_w   = (const float*)d_in[9];
    const float* low_b   = (const float*)d_in[10];
    const float* lf_w1   = (const float*)d_in[11];
    const float* lf_b1   = (const float*)d_in[12];
    const float* lf_ln_w = (const float*)d_in[13];
    const float* lf_ln_b = (const float*)d_in[14];
    const float* lf_w2   = (const float*)d_in[15];
    const float* lf_b2   = (const float*)d_in[16];

    void *pz, *pps, *pHh, *pHlf, *pktok, *pgate, *palpha, *pwt, *pwth, *psh, *psl, *pc1, *pbp;
    cudaGetSymbolAddress(&pz, g_z);
    cudaGetSymbolAddress(&pps, g_ps);
    cudaGetSymbolAddress(&pHh, g_Hh);
    cudaGetSymbolAddress(&pHlf, g_Hlf);
    cudaGetSymbolAddress(&pktok, g_ktok);
    cudaGetSymbolAddress(&pgate, g_gate);
    cudaGetSymbolAddress(&palpha, g_alpha);
    cudaGetSymbolAddress(&pwt, g_wt);
    cudaGetSymbolAddress(&pwth, g_wth);
    cudaGetSymbolAddress(&psh, g_stats_hf);
    cudaGetSymbolAddress(&psl, g_stats_lf);
    cudaGetSymbolAddress(&pc1, g_c1);
    cudaGetSymbolAddress(&pbp, g_bp);
    const float* wt = (const float*)pwt;
    const __nv_bfloat16* wth = (const __nv_bfloat16*)pwth;
    float2* sh = (float2*)psh;
    float2* sl = (float2*)psl;
    const float* c1 = (const float*)pc1;
    const float* bp = (const float*)pbp;

    cudaFuncSetAttribute((const void*)gemmh_kernel<256, 0, 1, 512>,
                         cudaFuncAttributeMaxDynamicSharedMemorySize, SMEM_H);
    cudaFuncSetAttribute((const void*)gemmh_kernel<512, 2, 2, 256>,
                         cudaFuncAttributeMaxDynamicSharedMemorySize, SMEM_H);
    cudaFuncSetAttribute((const void*)gemm256_kernel<512, 1, 0, 256>,
                         cudaFuncAttributeMaxDynamicSharedMemorySize, SMEM_G);
    cudaFuncSetAttribute((const void*)gemm256_kernel<256, 2, 1, 512>,
                         cudaFuncAttributeMaxDynamicSharedMemorySize, SMEM_G);
    cudaFuncSetAttribute((const void*)gemm256_kernel<512, 2, 3, 256>,
                         cudaFuncAttributeMaxDynamicSharedMemorySize, SMEM_G);

    transpose5_kernel<<<dim3(16, 16, 5), dim3(32, 8)>>>(hf_w1, hf_w2, low_w, lf_w1, lf_w2,
                                                        hf_ln_w, lf_ln_w);
    fold_kernel<<<2, 256>>>(hf_w2, hf_ln_b, hf_b2, lf_w2, lf_ln_b, lf_b2);
    haar_z_kernel<<<dim3(4, 256, 16), 256>>>(xb);
    pool_small_kernel<<<dim3(512, 16), 256>>>(xsm);

    // hf chain (bf16 tensor cores)
    gemmh_kernel<256, 0, 1, 512><<<dim3(M_HF / 64, 2), 256, SMEM_H>>>(
        (const __nv_bfloat16*)pz, wth, hf_b1, nullptr, pHh, sh, nullptr);
    gemmh_kernel<512, 2, 2, 256><<<dim3(M_HF / 64, 1), 256, SMEM_H>>>(
        (const __nv_bfloat16*)pHh, wth + 512 * 256, bp + 0, hf_pr, palpha, sh, c1 + 0);

    // lf chain (tf32, unchanged from R6)
    gemm256_kernel<512, 1, 0, 256><<<dim3(M_LF / 64, 1), 256, SMEM_G>>>(
        (const float*)pps, wt + 2 * 512 * 256, low_b, nullptr, (float*)pktok, nullptr, nullptr);
    gemm256_kernel<256, 2, 1, 512><<<dim3(M_LF / 64, 2), 256, SMEM_G>>>(
        (const float*)pktok, wt + 3 * 512 * 256, lf_b1, nullptr, (float*)pHlf, sl, nullptr);
    gemm256_kernel<512, 2, 3, 256><<<dim3(M_LF / 64, 1), 256, SMEM_G>>>(
        (const float*)pHlf, wt + 4 * 512 * 256, bp + 256, nullptr, (float*)pgate, sl, c1 + 256);

    final_kernel<<<dim3(16, 256, 16), 256>>>(xb, (float*)d_out);
}

// round 11
// speedup vs baseline: 1.6194x; 1.0189x over previous
#include <cuda_runtime.h>
#include <cuda_bf16.h>
#include <cstdint>
#include <math.h>

#define DEV_INLINE __device__ __forceinline__

static constexpr int B_ = 16, C_ = 256, H_ = 128, W_ = 128;
static constexpr int CS = 512;
static constexpr int TOK_HF = 1024;
static constexpr int M_HF = 3 * B_ * TOK_HF;     // 49152
static constexpr int M_LF = B_ * 256;            // 4096

// ---------------- scratch ----------------
__device__ __nv_bfloat16 g_z[3ULL * B_ * C_ * TOK_HF];   // [band][b][c][tok] bf16
__device__ float g_ps[(size_t)B_ * CS * 256];            // [b][s][tok]
__device__ __nv_bfloat16 g_Hh[(size_t)M_HF * 512];       // RAW hidden (hf) bf16
__device__ float g_Hlf[(size_t)M_LF * 512];              // RAW hidden (lf) fp32
__device__ float g_ktok[(size_t)M_LF * C_];
__device__ float g_gate[(size_t)M_LF * C_];
__device__ float g_alpha[3 * B_ * TOK_HF];
__device__ float g_wt[5ULL * 512 * 256];                 // transposed weights [n][k] fp32
__device__ __nv_bfloat16 g_wth[2ULL * 512 * 256];        // bf16: [0]=hf_w1t(512n,256k), [1]=hf_w2t'(256n,512k)
__device__ float2 g_stats_hf[(size_t)M_HF * 2];
__device__ float2 g_stats_lf[(size_t)M_LF * 2];
__device__ float g_c1[2 * 256];
__device__ float g_bp[2 * 256];

// ---------------- weight transpose (+ LN-weight folding + bf16 copies) ----------------
__global__ void transpose5_kernel(const float* __restrict__ w0, const float* __restrict__ w1,
                                  const float* __restrict__ w2, const float* __restrict__ w3,
                                  const float* __restrict__ w4,
                                  const float* __restrict__ hf_lnw, const float* __restrict__ lf_lnw)
{
    __shared__ float tile[32][33];
    int mi = blockIdx.z;
    const float* in; int R, Cc; const float* lnw = nullptr;
    switch (mi) {
        case 0: in = w0; R = 256; Cc = 512; break;                 // hf_w1 -> [512n][256k]
        case 1: in = w1; R = 512; Cc = 256; lnw = hf_lnw; break;   // hf_w2' -> [256n][512k]
        case 2: in = w2; R = 512; Cc = 256; break;
        case 3: in = w3; R = 256; Cc = 512; break;
        default: in = w4; R = 512; Cc = 256; lnw = lf_lnw; break;
    }
    float* out = g_wt + (size_t)mi * 512 * 256;
    int bx = blockIdx.x * 32, by = blockIdx.y * 32;
    if (bx >= Cc || by >= R) return;
    int tx = threadIdx.x, ty = threadIdx.y;
#pragma unroll
    for (int j = 0; j < 32; j += 8) {
        int row = by + ty + j;
        float v = in[(size_t)row * Cc + bx + tx];
        if (lnw) v *= __ldg(lnw + row);
        tile[ty + j][tx] = v;
    }
    __syncthreads();
#pragma unroll
    for (int j = 0; j < 32; j += 8) {
        float v = tile[tx][ty + j];
        size_t oidx = (size_t)(bx + ty + j) * R + by + tx;
        out[oidx] = v;
        if (mi == 0) g_wth[oidx] = __float2bfloat16(v);
        if (mi == 1) g_wth[512 * 256 + oidx] = __float2bfloat16(v);
    }
}

// fold: c1[n]=col-sums of W2'; bp[n]=b2[n]+lnb@W2
__global__ void fold_kernel(const float* __restrict__ w2a, const float* __restrict__ lnba,
                            const float* __restrict__ b2a,
                            const float* __restrict__ w2b, const float* __restrict__ lnbb,
                            const float* __restrict__ b2b)
{
    int mi = blockIdx.x;
    int n = threadIdx.x;
    const float* wt = g_wt + (size_t)(mi ? 4 : 1) * 512 * 256;
    const float* w2 = mi ? w2b : w2a;
    const float* lnb = mi ? lnbb : lnba;
    const float* b2 = mi ? b2b : b2a;
    float s1 = 0.f, s2 = 0.f;
    for (int k = 0; k < 512; k++) {
        s1 += wt[(size_t)n * 512 + k];
        s2 += lnb[k] * w2[(size_t)k * 256 + n];
    }
    g_c1[mi * 256 + n] = s1;
    g_bp[mi * 256 + n] = b2[n] + s2;
}

// ---------------- K1: Haar bands -> abs-pooled z tokens (bf16 out) ----------------
__global__ void haar_z_kernel(const float* __restrict__ xb)
{
    int tid = threadIdx.x;
    int tk = blockIdx.x * 256 + tid;
    int c = blockIdx.y, b = blockIdx.z;
    int ti = tk >> 5, tj = tk & 31;
    const float* base = xb + ((size_t)(b * C_ + c) * H_ + 4 * ti) * W_ + 4 * tj;
    float4 r0 = *(const float4*)(base);
    float4 r1 = *(const float4*)(base + W_);
    float4 r2 = *(const float4*)(base + 2 * W_);
    float4 r3 = *(const float4*)(base + 3 * W_);
    float zh = 0.f, zv = 0.f, zd = 0.f;
#define HBLK(p00, p01, p10, p11) \
    zh += fabsf((p00) - (p01) + (p10) - (p11)); \
    zv += fabsf((p00) + (p01) - (p10) - (p11)); \
    zd += fabsf((p00) - (p01) - (p10) + (p11));
    HBLK(r0.x, r0.y, r1.x, r1.y)
    HBLK(r0.z, r0.w, r1.z, r1.w)
    HBLK(r2.x, r2.y, r3.x, r3.y)
    HBLK(r2.z, r2.w, r3.z, r3.w)
#undef HBLK
    const float s = 0.0625f;
    size_t base_o = ((size_t)(b) * C_ + c) * TOK_HF + tk;
    const size_t BS = (size_t)B_ * C_ * TOK_HF;
    g_z[base_o]          = __float2bfloat16(zh * s);
    g_z[BS + base_o]     = __float2bfloat16(zv * s);
    g_z[2 * BS + base_o] = __float2bfloat16(zd * s);
}

// ---------------- K2: 4x4 mean-pool of x_small ----------------
__global__ void pool_small_kernel(const float* __restrict__ xsm)
{
    int s = blockIdx.x, b = blockIdx.y;
    const float* src = xsm + ((size_t)(b * CS + s)) * 64 * 64;
    int t = threadIdx.x;
    int tj = t & 15, ti = t >> 4;
    float sum = 0.f;
#pragma unroll
    for (int r = 0; r < 4; r++) {
        float4 v = *(const float4*)(src + (4 * ti + r) * 64 + 4 * tj);
        sum += v.x + v.y + v.z + v.w;
    }
    g_ps[((size_t)(b * CS + s)) * 256 + t] = sum * (1.f / 16.f);
}

// ---------------- asm helpers ----------------
DEV_INLINE void mma8(float* c, const unsigned* a, const unsigned* b) {
    asm volatile("mma.sync.aligned.m16n8k8.row.col.f32.tf32.tf32.f32 "
                 "{%0,%1,%2,%3}, {%4,%5,%6,%7}, {%8,%9}, {%0,%1,%2,%3};"
                 : "+f"(c[0]), "+f"(c[1]), "+f"(c[2]), "+f"(c[3])
                 : "r"(a[0]), "r"(a[1]), "r"(a[2]), "r"(a[3]),
                   "r"(b[0]), "r"(b[1]));
}
DEV_INLINE void mma16(float* c, const unsigned* a, const unsigned* b) {
    asm volatile("mma.sync.aligned.m16n8k16.row.col.f32.bf16.bf16.f32 "
                 "{%0,%1,%2,%3}, {%4,%5,%6,%7}, {%8,%9}, {%0,%1,%2,%3};"
                 : "+f"(c[0]), "+f"(c[1]), "+f"(c[2]), "+f"(c[3])
                 : "r"(a[0]), "r"(a[1]), "r"(a[2]), "r"(a[3]),
                   "r"(b[0]), "r"(b[1]));
}
DEV_INLINE void ldsm4(unsigned& r0, unsigned& r1, unsigned& r2, unsigned& r3, uint32_t addr) {
    asm volatile("ldmatrix.sync.aligned.m8n8.x4.shared.b16 {%0,%1,%2,%3}, [%4];"
                 : "=r"(r0), "=r"(r1), "=r"(r2), "=r"(r3) : "r"(addr));
}
DEV_INLINE void cp16(uint32_t s, const void* g) {
    asm volatile("cp.async.cg.shared.global [%0], [%1], 16;" :: "r"(s), "l"(g));
}
DEV_INLINE void cp_commit() { asm volatile("cp.async.commit_group;"); }
template<int NN> DEV_INLINE void cp_wait() { asm volatile("cp.async.wait_group %0;" :: "n"(NN)); }

// ---------------- tf32 64x256-tile GEMM (R6-proven, lf chain) ----------------
template<int K, int AMODE, int EPI, int OSTRIDE>
__global__ void __launch_bounds__(256, 2)
gemm256_kernel(const float* __restrict__ A, const float* __restrict__ Bt,
               const float* __restrict__ bias, const float* __restrict__ p0,
               float* __restrict__ out, float2* __restrict__ stats,
               const float* __restrict__ c1)
{
    constexpr int KC = 32, SW = 36, SWB = SW * 4, NIT = K / KC, NN = 256;
    constexpr int MT = 2;

    extern __shared__ __align__(16) float dsm[];
    float* As = dsm;
    float* Bs = As + 2 * 64 * SW;
    float* sred = Bs + 2 * NN * SW;
    float* ssred = sred + 256;

    int tid = threadIdx.x;
    int lane = tid & 31, warp = tid >> 5;
    int wn = warp & 3, wm = warp >> 2;
    int gid = lane >> 2, q4 = lane & 3;
    int m0 = blockIdx.x * 64;
    int n0 = blockIdx.y * 256;

    const float* Ab; int astride = 0;
    if (AMODE == 1) { Ab = A + (size_t)(m0 >> 8) * (CS * 256) + (m0 & 255); astride = 256; }
    else { Ab = A + (size_t)m0 * K; }
    const float* BtB = Bt + (size_t)n0 * K;

    uint32_t smem_a = (uint32_t)__cvta_generic_to_shared(As);
    uint32_t smem_b = (uint32_t)__cvta_generic_to_shared(Bs);

    int la_m = tid & 63, la_kg = tid >> 6;
    float areg[8];
    auto load_A = [&](int k0) {
        if (AMODE == 1) {
#pragma unroll
            for (int i = 0; i < 8; i++)
                areg[i] = __ldg(Ab + (size_t)(k0 + la_kg * 8 + i) * astride + la_m);
        }
    };
    auto sts_A = [&](int st) {
        if (AMODE == 1) {
            float* p = As + st * 64 * SW + la_m * SW + la_kg * 8;
            *(float4*)(p)     = make_float4(areg[0], areg[1], areg[2], areg[3]);
            *(float4*)(p + 4) = make_float4(areg[4], areg[5], areg[6], areg[7]);
        }
    };
    auto cp_stage = [&](int st, int k0) {
        if (AMODE == 2) {
#pragma unroll
            for (int j = 0; j < 2; j++) {
                int idx = tid + j * 256;
                int m = idx >> 3, kq = idx & 7;
                cp16(smem_a + (uint32_t)((st * 64 + m) * SW + kq * 4) * 4,
                     Ab + (size_t)m * K + k0 + kq * 4);
            }
        }
#pragma unroll
        for (int j = 0; j < 8; j++) {
            int idx = tid + j * 256;
            int n = idx >> 3, kc = idx & 7;
            cp16(smem_b + (uint32_t)((st * NN + n) * SW + kc * 4) * 4,
                 BtB + (size_t)n * K + k0 + kc * 4);
        }
        cp_commit();
    };

    int ra = lane & 15;
    int ca = (lane & 16) ? 16 : 0;
    int rb = (lane & 7) + ((lane >> 4) << 3);
    int cb = (lane & 8) ? 16 : 0;

    float acc[MT][8][4];
#pragma unroll
    for (int mi = 0; mi < MT; mi++)
#pragma unroll
        for (int ni = 0; ni < 8; ni++)
#pragma unroll
            for (int e = 0; e < 4; e++) acc[mi][ni][e] = 0.f;

    load_A(0);
    cp_stage(0, 0);
    sts_A(0);
    if (NIT > 1) load_A(KC);

    for (int it = 0; it < NIT; it++) {
        int cur = it & 1;
        bool more = (it + 1 < NIT);
        cp_wait<0>();
        __syncthreads();
        if (more) {
            cp_stage(cur ^ 1, (it + 1) * KC);
            sts_A(cur ^ 1);
        }
        if (it + 2 < NIT) load_A((it + 2) * KC);

        uint32_t abase = smem_a + (uint32_t)(cur * 64 * SW) * 4;
        uint32_t bbase = smem_b + (uint32_t)(cur * NN * SW) * 4;
#pragma unroll
        for (int kk = 0; kk < KC; kk += 8) {
            unsigned afr[MT][4];
#pragma unroll
            for (int mi = 0; mi < MT; mi++)
                ldsm4(afr[mi][0], afr[mi][1], afr[mi][2], afr[mi][3],
                      abase + (uint32_t)((wm * 32 + mi * 16 + ra) * SWB + kk * 4 + ca));
            unsigned bfr[8][2];
#pragma unroll
            for (int nis = 0; nis < 8; nis += 2)
                ldsm4(bfr[nis][0], bfr[nis][1], bfr[nis + 1][0], bfr[nis + 1][1],
                      bbase + (uint32_t)((wn * 64 + nis * 8 + rb) * SWB + kk * 4 + cb));
#pragma unroll
            for (int mi = 0; mi < MT; mi++)
#pragma unroll
                for (int ni = 0; ni < 8; ni++)
                    mma8(acc[mi][ni], afr[mi], bfr[ni]);
        }
    }

    float mu_rs[MT][2], rstd_v[MT][2];
    if (EPI == 3) {
#pragma unroll
        for (int mi = 0; mi < MT; mi++)
#pragma unroll
            for (int h = 0; h < 2; h++) {
                int lr = wm * 32 + mi * 16 + gid + h * 8;
                float2 s0 = stats[(size_t)(m0 + lr) * 2 + 0];
                float2 s1 = stats[(size_t)(m0 + lr) * 2 + 1];
                float sum = s0.x + s1.x, ss = s0.y + s1.y;
                float mu = sum * (1.f / 512.f);
                float var = ss * (1.f / 512.f) - mu * mu;
                float rstd = rsqrtf(var + 1e-5f);
                rstd_v[mi][h] = rstd;
                mu_rs[mi][h] = mu * rstd;
            }
    }

    float rs[MT][2], rss[MT][2];
#pragma unroll
    for (int mi = 0; mi < MT; mi++) { rs[mi][0] = rs[mi][1] = 0.f; rss[mi][0] = rss[mi][1] = 0.f; }

#pragma unroll
    for (int mi = 0; mi < MT; mi++)
#pragma unroll
        for (int ni = 0; ni < 8; ni++)
#pragma unroll
            for (int e4 = 0; e4 < 4; e4++) {
                int h = e4 >> 1, e = e4 & 1;
                int col = wn * 64 + ni * 8 + q4 * 2 + e;
                float v;
                if (EPI <= 1) {
                    v = acc[mi][ni][e4] + __ldg(bias + n0 + col);
                    if (EPI == 1) { rs[mi][h] += v; rss[mi][h] += v * v; }
                } else {
                    v = rstd_v[mi][h] * acc[mi][ni][e4] - mu_rs[mi][h] * __ldg(c1 + col)
                        + __ldg(bias + col);
                }
                acc[mi][ni][e4] = v;
            }

    if (EPI == 1) {
#pragma unroll
        for (int mi = 0; mi < MT; mi++)
#pragma unroll
            for (int h = 0; h < 2; h++) {
                float s = rs[mi][h], ss = rss[mi][h];
                s  += __shfl_xor_sync(0xffffffffu, s, 1);
                s  += __shfl_xor_sync(0xffffffffu, s, 2);
                ss += __shfl_xor_sync(0xffffffffu, ss, 1);
                ss += __shfl_xor_sync(0xffffffffu, ss, 2);
                if (q4 == 0) {
                    int lr = wm * 32 + mi * 16 + gid + h * 8;
                    sred[lr * 4 + wn] = s; ssred[lr * 4 + wn] = ss;
                }
            }
        __syncthreads();
    }

#pragma unroll
    for (int mi = 0; mi < MT; mi++)
#pragma unroll
        for (int ni = 0; ni < 8; ni++) {
            int col = wn * 64 + ni * 8 + q4 * 2;
#pragma unroll
            for (int h = 0; h < 2; h++) {
                int lr = wm * 32 + mi * 16 + gid + h * 8;
                float vx = acc[mi][ni][h * 2 + 0], vy = acc[mi][ni][h * 2 + 1];
                if (EPI == 3) { vx = 1.f / (1.f + expf(-vx)); vy = 1.f / (1.f + expf(-vy)); }
                *(float2*)(out + (size_t)(m0 + lr) * OSTRIDE + n0 + col) = make_float2(vx, vy);
            }
        }
    if (EPI == 1) {
        if (tid < 64) {
            float s = 0.f, ss = 0.f;
#pragma unroll
            for (int j = 0; j < 4; j++) { s += sred[tid * 4 + j]; ss += ssred[tid * 4 + j]; }
            stats[(size_t)(m0 + tid) * 2 + blockIdx.y] = make_float2(s, ss);
        }
    }
}

// ---------------- bf16 64x256-tile GEMM, KC=64 (hf chain) ----------------
// AMODE: 0 = z-layout bf16 ([blk][k][1024]); 2 = row-major bf16.
// EPI: 1 = +bias, store bf16 H + partial stats; 2 = LN-fold + cos-sim -> relu alpha.
template<int K, int AMODE, int EPI, int OSTRIDE>
__global__ void __launch_bounds__(256, 2)
gemmh_kernel(const __nv_bfloat16* __restrict__ A, const __nv_bfloat16* __restrict__ Bt,
             const float* __restrict__ bias, const float* __restrict__ p0,
             void* __restrict__ outv, float2* __restrict__ stats,
             const float* __restrict__ c1)
{
    constexpr int KC = 64, SW = 72 /*halves*/, SWB = SW * 2 /*144 B*/, NIT = K / KC, NN = 256;
    constexpr int MT = 2;

    extern __shared__ __align__(16) char dsmh[];
    __nv_bfloat16* As = (__nv_bfloat16*)dsmh;            // 2*64*72 halves
    __nv_bfloat16* Bs = As + 2 * 64 * SW;                // 2*256*72 halves
    float* sred = (float*)(Bs + 2 * NN * SW);
    float* ssred = sred + 256;
    float* spn = ssred + 256;

    int tid = threadIdx.x;
    int lane = tid & 31, warp = tid >> 5;
    int wn = warp & 3, wm = warp >> 2;
    int gid = lane >> 2, q4 = lane & 3;
    int m0 = blockIdx.x * 64;
    int n0 = blockIdx.y * 256;

    const __nv_bfloat16* Ab; int astride = 0;
    if (AMODE == 0) { Ab = A + (size_t)(m0 >> 10) * (C_ * TOK_HF) + (m0 & 1023); astride = TOK_HF; }
    else { Ab = A + (size_t)m0 * K; }
    const __nv_bfloat16* BtB = Bt + (size_t)n0 * K;

    if (EPI == 2 && warp == 0) {
        float s = 0.f;
        for (int i = lane; i < 256; i += 32) { float v = __ldg(p0 + i); s += v * v; }
#pragma unroll
        for (int o = 16; o; o >>= 1) s += __shfl_xor_sync(0xffffffffu, s, o);
        if (lane == 0) *spn = sqrtf(s);
    }

    uint32_t smem_a = (uint32_t)__cvta_generic_to_shared(As);
    uint32_t smem_b = (uint32_t)__cvta_generic_to_shared(Bs);

    int la_m = tid & 63, la_kg = tid >> 6;     // 4 k-groups of 16 halves
    unsigned areg[8];
    auto load_A = [&](int k0) {
        if (AMODE == 0) {
            const unsigned short* Au = (const unsigned short*)Ab;
            unsigned short h[16];
#pragma unroll
            for (int i = 0; i < 16; i++)
                h[i] = __ldg(Au + (size_t)(k0 + la_kg * 16 + i) * astride + la_m);
#pragma unroll
            for (int j = 0; j < 8; j++)
                areg[j] = (unsigned)h[2 * j] | ((unsigned)h[2 * j + 1] << 16);
        }
    };
    auto sts_A = [&](int st) {
        if (AMODE == 0) {
            uint4* p = (uint4*)(As + (size_t)(st * 64 + la_m) * SW + la_kg * 16);
            p[0] = make_uint4(areg[0], areg[1], areg[2], areg[3]);
            p[1] = make_uint4(areg[4], areg[5], areg[6], areg[7]);
        }
    };
    auto cp_stage = [&](int st, int k0) {
        if (AMODE == 2) {
#pragma unroll
            for (int j = 0; j < 2; j++) {      // 64 m x 8 chunks of 8 halves
                int idx = tid + j * 256;
                int m = idx >> 3, kq = idx & 7;
                cp16(smem_a + (uint32_t)((st * 64 + m) * SW + kq * 8) * 2,
                     Ab + (size_t)m * K + k0 + kq * 8);
            }
        }
#pragma unroll
        for (int j = 0; j < 8; j++) {          // 256 n x 8 chunks
            int idx = tid + j * 256;
            int n = idx >> 3, kc = idx & 7;
            cp16(smem_b + (uint32_t)((st * NN + n) * SW + kc * 8) * 2,
                 BtB + (size_t)n * K + k0 + kc * 8);
        }
        cp_commit();
    };

    int ra = lane & 15;
    int ca = (lane >> 4) * 16;                  // byte offset: second 8 k-halves of the k16 step
    int rb = (lane & 7) + ((lane >> 4) << 3);
    int cb = (lane & 8) ? 16 : 0;

    float acc[MT][8][4];
#pragma unroll
    for (int mi = 0; mi < MT; mi++)
#pragma unroll
        for (int ni = 0; ni < 8; ni++)
#pragma unroll
            for (int e = 0; e < 4; e++) acc[mi][ni][e] = 0.f;

    load_A(0);
    cp_stage(0, 0);
    sts_A(0);
    if (NIT > 1) load_A(KC);

    for (int it = 0; it < NIT; it++) {
        int cur = it & 1;
        bool more = (it + 1 < NIT);
        cp_wait<0>();
        __syncthreads();
        if (more) {
            cp_stage(cur ^ 1, (it + 1) * KC);
            sts_A(cur ^ 1);
        }
        if (it + 2 < NIT) load_A((it + 2) * KC);

        uint32_t abase = smem_a + (uint32_t)(cur * 64 * SW) * 2;
        uint32_t bbase = smem_b + (uint32_t)(cur * NN * SW) * 2;
#pragma unroll
        for (int kk = 0; kk < 4; kk++) {        // four k16 steps
            unsigned afr[MT][4];
#pragma unroll
            for (int mi = 0; mi < MT; mi++)
                ldsm4(afr[mi][0], afr[mi][1], afr[mi][2], afr[mi][3],
                      abase + (uint32_t)((wm * 32 + mi * 16 + ra) * SWB + ca + kk * 32));
            unsigned bfr[8][2];
#pragma unroll
            for (int nis = 0; nis < 8; nis += 2)
                ldsm4(bfr[nis][0], bfr[nis][1], bfr[nis + 1][0], bfr[nis + 1][1],
                      bbase + (uint32_t)((wn * 64 + nis * 8 + rb) * SWB + cb + kk * 32));
#pragma unroll
            for (int mi = 0; mi < MT; mi++)
#pragma unroll
                for (int ni = 0; ni < 8; ni++)
                    mma16(acc[mi][ni], afr[mi], bfr[ni]);
        }
    }

    // ---- epilogue ----
    float mu_rs[MT][2], rstd_v[MT][2];
    if (EPI == 2) {
#pragma unroll
        for (int mi = 0; mi < MT; mi++)
#pragma unroll
            for (int h = 0; h < 2; h++) {
                int lr = wm * 32 + mi * 16 + gid + h * 8;
                float2 s0 = stats[(size_t)(m0 + lr) * 2 + 0];
                float2 s1 = stats[(size_t)(m0 + lr) * 2 + 1];
                float sum = s0.x + s1.x, ss = s0.y + s1.y;
                float mu = sum * (1.f / 512.f);
                float var = ss * (1.f / 512.f) - mu * mu;
                float rstd = rsqrtf(var + 1e-5f);
                rstd_v[mi][h] = rstd;
                mu_rs[mi][h] = mu * rstd;
            }
    }

    float rs[MT][2], rss[MT][2];
#pragma unroll
    for (int mi = 0; mi < MT; mi++) { rs[mi][0] = rs[mi][1] = 0.f; rss[mi][0] = rss[mi][1] = 0.f; }

#pragma unroll
    for (int mi = 0; mi < MT; mi++)
#pragma unroll
        for (int ni = 0; ni < 8; ni++)
#pragma unroll
            for (int e4 = 0; e4 < 4; e4++) {
                int h = e4 >> 1, e = e4 & 1;
                int col = wn * 64 + ni * 8 + q4 * 2 + e;
                float v;
                if (EPI == 1) {
                    v = acc[mi][ni][e4] + __ldg(bias + n0 + col);
                    rs[mi][h] += v; rss[mi][h] += v * v;
                } else {
                    v = rstd_v[mi][h] * acc[mi][ni][e4] - mu_rs[mi][h] * __ldg(c1 + col)
                        + __ldg(bias + col);
                    rs[mi][h] += v * __ldg(p0 + col); rss[mi][h] += v * v;
                }
                acc[mi][ni][e4] = v;
            }

#pragma unroll
    for (int mi = 0; mi < MT; mi++)
#pragma unroll
        for (int h = 0; h < 2; h++) {
            float s = rs[mi][h], ss = rss[mi][h];
            s  += __shfl_xor_sync(0xffffffffu, s, 1);
            s  += __shfl_xor_sync(0xffffffffu, s, 2);
            ss += __shfl_xor_sync(0xffffffffu, ss, 1);
            ss += __shfl_xor_sync(0xffffffffu, ss, 2);
            if (q4 == 0) {
                int lr = wm * 32 + mi * 16 + gid + h * 8;
                sred[lr * 4 + wn] = s; ssred[lr * 4 + wn] = ss;
            }
        }
    __syncthreads();

    if (EPI == 1) {
        __nv_bfloat16* outp = (__nv_bfloat16*)outv;
#pragma unroll
        for (int mi = 0; mi < MT; mi++)
#pragma unroll
            for (int ni = 0; ni < 8; ni++) {
                int col = wn * 64 + ni * 8 + q4 * 2;
#pragma unroll
                for (int h = 0; h < 2; h++) {
                    int lr = wm * 32 + mi * 16 + gid + h * 8;
                    *(__nv_bfloat162*)(outp + (size_t)(m0 + lr) * OSTRIDE + n0 + col) =
                        __floats2bfloat162_rn(acc[mi][ni][h * 2 + 0], acc[mi][ni][h * 2 + 1]);
                }
            }
        if (tid < 64) {
            float s = 0.f, ss = 0.f;
#pragma unroll
            for (int j = 0; j < 4; j++) { s += sred[tid * 4 + j]; ss += ssred[tid * 4 + j]; }
            stats[(size_t)(m0 + tid) * 2 + blockIdx.y] = make_float2(s, ss);
        }
    }
    if (EPI == 2) {
        if (tid < 64) {
            float dot = 0.f, nsq = 0.f;
#pragma unroll
            for (int j = 0; j < 4; j++) { dot += sred[tid * 4 + j]; nsq += ssred[tid * 4 + j]; }
            float nq = sqrtf(nsq);
            float sim = dot / (fmaxf(nq, 1e-8f) * fmaxf(*spn, 1e-8f));
            ((float*)outv)[m0 + tid] = fmaxf(sim, 0.f);
        }
    }
}

// ---------------- K5: apply alpha/gate, inverse Haar, write output ----------------
__global__ void final_kernel(const float* __restrict__ xb, float* __restrict__ out)
{
    __shared__ __align__(16) float xs[8 * 128];
    int bi = blockIdx.x, c = blockIdx.y, b = blockIdx.z;
    size_t img = ((size_t)(b * C_ + c)) * H_;
    int t = threadIdx.x;
    int lrow = t >> 5, lcol = t & 31;
    ((float4*)xs)[t] = ((const float4*)(xb + (img + 8 * bi + lrow) * W_))[lcol];
    __syncthreads();
    int rp = t >> 6, j = t & 63;
    float2 top = ((const float2*)(xs + (2 * rp) * W_))[j];
    float2 bot = ((const float2*)(xs + (2 * rp + 1) * W_))[j];
    float p00 = top.x, p01 = top.y, p10 = bot.x, p11 = bot.y;
    float a  = 0.25f * (p00 + p01 + p10 + p11);
    float hb = 0.25f * (p00 - p01 + p10 - p11);
    float vb = 0.25f * (p00 + p01 - p10 - p11);
    float db = 0.25f * (p00 - p01 - p10 + p11);
    int hr = 4 * bi + rp, hc = j;
    int tok = (hr >> 1) * 32 + (hc >> 1);
    float ah = __ldg(&g_alpha[(0 * B_ + b) * TOK_HF + tok]);
    float av = __ldg(&g_alpha[(1 * B_ + b) * TOK_HF + tok]);
    float ad = __ldg(&g_alpha[(2 * B_ + b) * TOK_HF + tok]);
    int tg = (hr >> 2) * 16 + (hc >> 2);
    float gt = __ldg(&g_gate[((size_t)(b * 256 + tg)) * C_ + c]);
    float ae = a * gt, he = hb * ah, ve = vb * av, de = db * ad;
    float2 o0 = make_float2(ae + he + ve + de, ae - he + ve - de);
    float2 o1 = make_float2(ae + he - ve - de, ae - he - ve + de);
    int row0 = 8 * bi + 2 * rp;
    ((float2*)(out + (img + row0) * W_))[j] = o0;
    ((float2*)(out + (img + row0 + 1) * W_))[j] = o1;
}

static constexpr int SMEM_G = (2 * 64 * 36 + 2 * 256 * 36 + 512 + 4) * 4;       // ~92 KB
static constexpr int SMEM_H = (2 * 64 * 72 + 2 * 256 * 72) * 2 + (512 + 4) * 4; // ~92 KB

extern "C" void kernel_launch(void* const* d_in, const int* in_sizes, int n_in,
                              void* d_out, int out_size)
{
    const float* xb      = (const float*)d_in[0];
    const float* xsm     = (const float*)d_in[1];
    const float* hf_w1   = (const float*)d_in[2];
    const float* hf_b1   = (const float*)d_in[3];
    const float* hf_ln_w = (const float*)d_in[4];
    const float* hf_ln_b = (const float*)d_in[5];
    const float* hf_w2   = (const float*)d_in[6];
    const float* hf_b2   = (const float*)d_in[7];
    const float* hf_pr   = (const float*)d_in[8];
    const float* low_w   = (const float*)d_in[9];
    const float* low_b   = (const float*)d_in[10];
    const float* lf_w1   = (const float*)d_in[11];
    const float* lf_b1   = (const float*)d_in[12];
    const float* lf_ln_w = (const float*)d_in[13];
    const float* lf_ln_b = (const float*)d_in[14];
    const float* lf_w2   = (const float*)d_in[15];
    const float* lf_b2   = (const float*)d_in[16];

    void *pz, *pps, *pHh, *pHlf, *pktok, *pgate, *palpha, *pwt, *pwth, *psh, *psl, *pc1, *pbp;
    cudaGetSymbolAddress(&pz, g_z);
    cudaGetSymbolAddress(&pps, g_ps);
    cudaGetSymbolAddress(&pHh, g_Hh);
    cudaGetSymbolAddress(&pHlf, g_Hlf);
    cudaGetSymbolAddress(&pktok, g_ktok);
    cudaGetSymbolAddress(&pgate, g_gate);
    cudaGetSymbolAddress(&palpha, g_alpha);
    cudaGetSymbolAddress(&pwt, g_wt);
    cudaGetSymbolAddress(&pwth, g_wth);
    cudaGetSymbolAddress(&psh, g_stats_hf);
    cudaGetSymbolAddress(&psl, g_stats_lf);
    cudaGetSymbolAddress(&pc1, g_c1);
    cudaGetSymbolAddress(&pbp, g_bp);
    const float* wt = (const float*)pwt;
    const __nv_bfloat16* wth = (const __nv_bfloat16*)pwth;
    float2* sh = (float2*)psh;
    float2* sl = (float2*)psl;
    const float* c1 = (const float*)pc1;
    const float* bp = (const float*)pbp;

    cudaFuncSetAttribute((const void*)gemmh_kernel<256, 0, 1, 512>,
                         cudaFuncAttributeMaxDynamicSharedMemorySize, SMEM_H);
    cudaFuncSetAttribute((const void*)gemmh_kernel<512, 2, 2, 256>,
                         cudaFuncAttributeMaxDynamicSharedMemorySize, SMEM_H);
    cudaFuncSetAttribute((const void*)gemm256_kernel<512, 1, 0, 256>,
                         cudaFuncAttributeMaxDynamicSharedMemorySize, SMEM_G);
    cudaFuncSetAttribute((const void*)gemm256_kernel<256, 2, 1, 512>,
                         cudaFuncAttributeMaxDynamicSharedMemorySize, SMEM_G);
    cudaFuncSetAttribute((const void*)gemm256_kernel<512, 2, 3, 256>,
                         cudaFuncAttributeMaxDynamicSharedMemorySize, SMEM_G);

    // Launch order chosen so gemmh GEMM1 is the 4th launch (ncu profiles launch #4+skip).
    transpose5_kernel<<<dim3(16, 16, 5), dim3(32, 8)>>>(hf_w1, hf_w2, low_w, lf_w1, lf_w2,
                                                        hf_ln_w, lf_ln_w);
    haar_z_kernel<<<dim3(4, 256, 16), 256>>>(xb);
    fold_kernel<<<2, 256>>>(hf_w2, hf_ln_b, hf_b2, lf_w2, lf_ln_b, lf_b2);

    // hf chain (bf16 tensor cores, KC=64)
    gemmh_kernel<256, 0, 1, 512><<<dim3(M_HF / 64, 2), 256, SMEM_H>>>(
        (const __nv_bfloat16*)pz, wth, hf_b1, nullptr, pHh, sh, nullptr);
    pool_small_kernel<<<dim3(512, 16), 256>>>(xsm);
    gemmh_kernel<512, 2, 2, 256><<<dim3(M_HF / 64, 1), 256, SMEM_H>>>(
        (const __nv_bfloat16*)pHh, wth + 512 * 256, bp + 0, hf_pr, palpha, sh, c1 + 0);

    // lf chain (tf32, unchanged from R6)
    gemm256_kernel<512, 1, 0, 256><<<dim3(M_LF / 64, 1), 256, SMEM_G>>>(
        (const float*)pps, wt + 2 * 512 * 256, low_b, nullptr, (float*)pktok, nullptr, nullptr);
    gemm256_kernel<256, 2, 1, 512><<<dim3(M_LF / 64, 2), 256, SMEM_G>>>(
        (const float*)pktok, wt + 3 * 512 * 256, lf_b1, nullptr, (float*)pHlf, sl, nullptr);
    gemm256_kernel<512, 2, 3, 256><<<dim3(M_LF / 64, 1), 256, SMEM_G>>>(
        (const float*)pHlf, wt + 4 * 512 * 256, bp + 256, nullptr, (float*)pgate, sl, c1 + 256);

    final_kernel<<<dim3(16, 256, 16), 256>>>(xb, (float*)d_out);
}